// round 1
// baseline (speedup 1.0000x reference)
#include <cuda_runtime.h>
#include <math.h>
#include <stdint.h>

#define N_TEAMS 200000
#define D 16
#define N_EDGES 3200000
#define E_TOT (N_EDGES + N_TEAMS)
#define BATCH 500000
#define NEG_SLOPE 0.01f

// ---------------- scratch (device globals; no allocation allowed) ----------
__device__ float g_xn[N_TEAMS * D];     // normalized features
__device__ float g_alpha[E_TOT];        // per-edge alpha, then exp(alpha-m)
__device__ float g_m[N_TEAMS];          // segment max
__device__ float g_denom[N_TEAMS];      // segment sum
__device__ float g_x1[N_TEAMS * D];     // layer1 output (post leaky)
__device__ float g_x2[N_TEAMS * D];     // layer2 output (post leaky)
__device__ float g_colmax[3];
__device__ float g_colsum[3];

// ---------------- helpers --------------------------------------------------
__device__ __forceinline__ void atomicMaxF(float* addr, float v) {
    // standard signed/unsigned split trick; correct under interleaving
    if (v >= 0.0f) atomicMax((int*)addr, __float_as_int(v));
    else           atomicMin((unsigned int*)addr, __float_as_uint(v));
}

__device__ __forceinline__ float leaky(float v) {
    return v > 0.0f ? v : NEG_SLOPE * v;
}

__device__ __forceinline__ float warpMax(float v) {
    #pragma unroll
    for (int o = 16; o; o >>= 1) v = fmaxf(v, __shfl_xor_sync(0xffffffffu, v, o));
    return v;
}
__device__ __forceinline__ float warpSum(float v) {
    #pragma unroll
    for (int o = 16; o; o >>= 1) v += __shfl_xor_sync(0xffffffffu, v, o);
    return v;
}

// ---------------- kernels --------------------------------------------------

// zero y[N*D], m=-inf, denom=0; optionally init col stats
__global__ void k_init(float* __restrict__ y, int n, int init_cols) {
    int i = blockIdx.x * blockDim.x + threadIdx.x;
    if (i < n * D) y[i] = 0.0f;
    if (i < n) {
        g_m[i] = -INFINITY;
        g_denom[i] = 0.0f;
    }
    if (init_cols && i < 3) {
        g_colmax[i] = -INFINITY;
        g_colsum[i] = 0.0f;
    }
}

// xn = x / max(||x||, 1e-12), one thread per node
__global__ void k_normalize(const float* __restrict__ x, int n) {
    int i = blockIdx.x * blockDim.x + threadIdx.x;
    if (i >= n) return;
    const float4* xr = (const float4*)(x + (size_t)i * D);
    float4 a = xr[0], b = xr[1], c = xr[2], d = xr[3];
    float ss = a.x*a.x + a.y*a.y + a.z*a.z + a.w*a.w
             + b.x*b.x + b.y*b.y + b.z*b.z + b.w*b.w
             + c.x*c.x + c.y*c.y + c.z*c.z + c.w*c.w
             + d.x*d.x + d.y*d.y + d.z*d.z + d.w*d.w;
    float inv = 1.0f / fmaxf(sqrtf(ss), 1e-12f);
    float4* o = (float4*)(g_xn + (size_t)i * D);
    a.x*=inv; a.y*=inv; a.z*=inv; a.w*=inv;
    b.x*=inv; b.y*=inv; b.z*=inv; b.w*=inv;
    c.x*=inv; c.y*=inv; c.z*=inv; c.w*=inv;
    d.x*=inv; d.y*=inv; d.z*=inv; d.w*=inv;
    o[0]=a; o[1]=b; o[2]=c; o[3]=d;
}

__device__ __forceinline__ void edge_st(int e, const int* __restrict__ es,
                                        const int* __restrict__ ed,
                                        int n_edges, int& s, int& t) {
    if (e < n_edges) { s = es[e]; t = ed[e]; }
    else             { s = t = e - n_edges; }
}

// alpha = beta * dot(xn[s], xn[t]); atomic segment max
__global__ void k_edge_alpha(const int* __restrict__ es, const int* __restrict__ ed,
                             const float* __restrict__ beta_p, int beta_idx,
                             int n_edges, int e_tot) {
    int e = blockIdx.x * blockDim.x + threadIdx.x;
    if (e >= e_tot) return;
    int s, t; edge_st(e, es, ed, n_edges, s, t);
    const float4* xs = (const float4*)(g_xn + (size_t)s * D);
    const float4* xt = (const float4*)(g_xn + (size_t)t * D);
    float dot = 0.0f;
    #pragma unroll
    for (int k = 0; k < 4; k++) {
        float4 a = xs[k], b = xt[k];
        dot += a.x*b.x + a.y*b.y + a.z*b.z + a.w*b.w;
    }
    float alpha = __ldg(beta_p + beta_idx) * dot;
    g_alpha[e] = alpha;
    atomicMaxF(&g_m[t], alpha);
}

// a = exp(alpha - m[t]); atomic segment sum
__global__ void k_edge_exp(const int* __restrict__ es, const int* __restrict__ ed,
                           int n_edges, int e_tot) {
    int e = blockIdx.x * blockDim.x + threadIdx.x;
    if (e >= e_tot) return;
    int s, t; edge_st(e, es, ed, n_edges, s, t);
    (void)s;
    float a = expf(g_alpha[e] - g_m[t]);
    g_alpha[e] = a;
    atomicAdd(&g_denom[t], a);
}

// y[t] += (a/denom[t]) * x[s]  — one thread per (edge, dim)
__global__ void k_edge_accum(const int* __restrict__ es, const int* __restrict__ ed,
                             const float* __restrict__ x, float* __restrict__ y,
                             int n_edges, int e_tot) {
    long long i = (long long)blockIdx.x * blockDim.x + threadIdx.x;
    int e = (int)(i >> 4);
    int dd = (int)(i & 15);
    if (e >= e_tot) return;
    int s, t; edge_st(e, es, ed, n_edges, s, t);
    float w = g_alpha[e] / (g_denom[t] + 1e-16f);
    atomicAdd(&y[(size_t)t * D + dd], w * x[(size_t)s * D + dd]);
}

__global__ void k_leaky(float* __restrict__ y, int n) {
    int i = blockIdx.x * blockDim.x + threadIdx.x;
    if (i < n) y[i] = leaky(y[i]);
}

// per-row MLP: concat(x[home], x[away]) -> 6 -> 16 -> 3 (leaky each)
__global__ void k_mlp(const float* __restrict__ x,
                      const int* __restrict__ home, const int* __restrict__ away,
                      const float* __restrict__ w0, const float* __restrict__ b0,
                      const float* __restrict__ w1, const float* __restrict__ b1,
                      const float* __restrict__ w2, const float* __restrict__ b2,
                      float* __restrict__ out, int batch) {
    int i = blockIdx.x * blockDim.x + threadIdx.x;
    if (i >= batch) return;
    float h0[32];
    {
        const float4* hr = (const float4*)(x + (size_t)home[i] * D);
        const float4* ar = (const float4*)(x + (size_t)away[i] * D);
        #pragma unroll
        for (int k = 0; k < 4; k++) {
            float4 v = hr[k];
            h0[4*k+0]=v.x; h0[4*k+1]=v.y; h0[4*k+2]=v.z; h0[4*k+3]=v.w;
        }
        #pragma unroll
        for (int k = 0; k < 4; k++) {
            float4 v = ar[k];
            h0[16+4*k+0]=v.x; h0[16+4*k+1]=v.y; h0[16+4*k+2]=v.z; h0[16+4*k+3]=v.w;
        }
    }
    float h1[6];
    #pragma unroll
    for (int j = 0; j < 6; j++) {
        float acc = __ldg(b0 + j);
        #pragma unroll
        for (int k = 0; k < 32; k++) acc += h0[k] * __ldg(w0 + k*6 + j);
        h1[j] = leaky(acc);
    }
    float h2[16];
    #pragma unroll
    for (int j = 0; j < 16; j++) {
        float acc = __ldg(b1 + j);
        #pragma unroll
        for (int k = 0; k < 6; k++) acc += h1[k] * __ldg(w1 + k*16 + j);
        h2[j] = leaky(acc);
    }
    #pragma unroll
    for (int j = 0; j < 3; j++) {
        float acc = __ldg(b2 + j);
        #pragma unroll
        for (int k = 0; k < 16; k++) acc += h2[k] * __ldg(w2 + k*3 + j);
        out[(size_t)i * 3 + j] = leaky(acc);
    }
}

// column max over dim 0 of out[B,3]
__global__ void k_colmax(const float* __restrict__ h, int batch) {
    float lm[3] = {-INFINITY, -INFINITY, -INFINITY};
    for (int i = blockIdx.x * blockDim.x + threadIdx.x; i < batch;
         i += gridDim.x * blockDim.x) {
        lm[0] = fmaxf(lm[0], h[(size_t)i*3+0]);
        lm[1] = fmaxf(lm[1], h[(size_t)i*3+1]);
        lm[2] = fmaxf(lm[2], h[(size_t)i*3+2]);
    }
    __shared__ float sm[3][8];
    int w = threadIdx.x >> 5, l = threadIdx.x & 31;
    #pragma unroll
    for (int j = 0; j < 3; j++) {
        float v = warpMax(lm[j]);
        if (l == 0) sm[j][w] = v;
    }
    __syncthreads();
    if (threadIdx.x == 0) {
        #pragma unroll
        for (int j = 0; j < 3; j++) {
            float v = sm[j][0];
            #pragma unroll
            for (int k = 1; k < 8; k++) v = fmaxf(v, sm[j][k]);
            atomicMaxF(&g_colmax[j], v);
        }
    }
}

__global__ void k_colsum(const float* __restrict__ h, int batch) {
    float m0 = g_colmax[0], m1 = g_colmax[1], m2 = g_colmax[2];
    float ls[3] = {0.0f, 0.0f, 0.0f};
    for (int i = blockIdx.x * blockDim.x + threadIdx.x; i < batch;
         i += gridDim.x * blockDim.x) {
        ls[0] += expf(h[(size_t)i*3+0] - m0);
        ls[1] += expf(h[(size_t)i*3+1] - m1);
        ls[2] += expf(h[(size_t)i*3+2] - m2);
    }
    __shared__ float sm[3][8];
    int w = threadIdx.x >> 5, l = threadIdx.x & 31;
    #pragma unroll
    for (int j = 0; j < 3; j++) {
        float v = warpSum(ls[j]);
        if (l == 0) sm[j][w] = v;
    }
    __syncthreads();
    if (threadIdx.x == 0) {
        #pragma unroll
        for (int j = 0; j < 3; j++) {
            float v = 0.0f;
            #pragma unroll
            for (int k = 0; k < 8; k++) v += sm[j][k];
            atomicAdd(&g_colsum[j], v);
        }
    }
}

__global__ void k_logsoftmax_final(float* __restrict__ out, int batch) {
    int i = blockIdx.x * blockDim.x + threadIdx.x;
    if (i >= batch * 3) return;
    int j = i % 3;
    out[i] = out[i] - g_colmax[j] - logf(g_colsum[j]);
}

// ---------------- launch ----------------------------------------------------
extern "C" void kernel_launch(void* const* d_in, const int* in_sizes, int n_in,
                              void* d_out, int out_size) {
    const float* embed  = (const float*)d_in[0];
    const float* beta   = (const float*)d_in[1];
    const float* w0     = (const float*)d_in[2];
    const float* b0     = (const float*)d_in[3];
    const float* w1     = (const float*)d_in[4];
    const float* b1     = (const float*)d_in[5];
    const float* w2     = (const float*)d_in[6];
    const float* b2     = (const float*)d_in[7];
    const int*   eidx   = (const int*)d_in[8];
    const int*   home   = (const int*)d_in[9];
    const int*   away   = (const int*)d_in[10];
    float* out = (float*)d_out;

    const int n      = in_sizes[0] / D;          // 200000
    const int nedges = in_sizes[8] / 2;          // 3200000
    const int etot   = nedges + n;
    const int batch  = in_sizes[9];              // 500000

    const int* es = eidx;            // row 0: src
    const int* ed = eidx + nedges;   // row 1: dst

    float* xn_scratch; cudaGetSymbolAddress((void**)&xn_scratch, g_xn);
    float* x1; cudaGetSymbolAddress((void**)&x1, g_x1);
    float* x2; cudaGetSymbolAddress((void**)&x2, g_x2);

    const int TB = 256;
    int gN   = (n + TB - 1) / TB;
    int gND  = (n * D + TB - 1) / TB;
    int gE   = (etot + TB - 1) / TB;
    long long accw = (long long)etot * D;
    int gEA  = (int)((accw + TB - 1) / TB);
    int gB   = (batch + TB - 1) / TB;
    int gB3  = (batch * 3 + TB - 1) / TB;

    // ---- layer 1: x0 = embed ----
    k_init<<<gND, TB>>>(x1, n, 1);
    k_normalize<<<gN, TB>>>(embed, n);
    k_edge_alpha<<<gE, TB>>>(es, ed, beta, 0, nedges, etot);
    k_edge_exp<<<gE, TB>>>(es, ed, nedges, etot);
    k_edge_accum<<<gEA, TB>>>(es, ed, embed, x1, nedges, etot);
    k_leaky<<<gND, TB>>>(x1, n * D);

    // ---- layer 2: input x1 ----
    k_init<<<gND, TB>>>(x2, n, 0);
    k_normalize<<<gN, TB>>>(x1, n);
    k_edge_alpha<<<gE, TB>>>(es, ed, beta, 1, nedges, etot);
    k_edge_exp<<<gE, TB>>>(es, ed, nedges, etot);
    k_edge_accum<<<gEA, TB>>>(es, ed, x1, x2, nedges, etot);
    k_leaky<<<gND, TB>>>(x2, n * D);

    // ---- MLP + log_softmax(dim=0) ----
    k_mlp<<<gB, TB>>>(x2, home, away, w0, b0, w1, b1, w2, b2, out, batch);
    k_colmax<<<512, TB>>>(out, batch);
    k_colsum<<<512, TB>>>(out, batch);
    k_logsoftmax_final<<<gB3, TB>>>(out, batch);
}

// round 2
// speedup vs baseline: 1.4647x; 1.4647x over previous
#include <cuda_runtime.h>
#include <math.h>
#include <stdint.h>

#define N_TEAMS 200000
#define D 16
#define N_EDGES 3200000
#define E_TOT (N_EDGES + N_TEAMS)
#define NEG_SLOPE 0.01f
#define CSB 512   // col-stat blocks

// ---------------- scratch (device globals; no allocation allowed) ----------
__device__ float g_xn[N_TEAMS * D];     // normalized features
__device__ float g_alpha[E_TOT];        // exp(alpha) per edge
__device__ float g_denom[N_TEAMS];      // segment sum -> reciprocal (in place)
__device__ float g_x1[N_TEAMS * D];     // layer1 output
__device__ float g_x2[N_TEAMS * D];     // layer2 output
__device__ float g_bmax[CSB * 3];
__device__ float g_bsum[CSB * 3];
__device__ float g_cls[3];              // colmax + log(colsum)

// ---------------- helpers --------------------------------------------------
__device__ __forceinline__ float leaky(float v) {
    return v > 0.0f ? v : NEG_SLOPE * v;
}
__device__ __forceinline__ float warpMax(float v) {
    #pragma unroll
    for (int o = 16; o; o >>= 1) v = fmaxf(v, __shfl_xor_sync(0xffffffffu, v, o));
    return v;
}
__device__ __forceinline__ float warpSum(float v) {
    #pragma unroll
    for (int o = 16; o; o >>= 1) v += __shfl_xor_sync(0xffffffffu, v, o);
    return v;
}
__device__ __forceinline__ void edge_st(int e, const int* __restrict__ es,
                                        const int* __restrict__ ed,
                                        int n_edges, int& s, int& t) {
    if (e < n_edges) { s = es[e]; t = ed[e]; }
    else             { s = t = e - n_edges; }
}

// ---------------- kernels --------------------------------------------------

// zero y[N*D] and denom[N]
__global__ void k_init(float* __restrict__ y, int n) {
    int i = blockIdx.x * blockDim.x + threadIdx.x;
    if (i < n * D) y[i] = 0.0f;
    if (i < n) g_denom[i] = 0.0f;
}

// xn = x / max(||x||, 1e-12)
__global__ void k_normalize(const float* __restrict__ x, int n) {
    int i = blockIdx.x * blockDim.x + threadIdx.x;
    if (i >= n) return;
    const float4* xr = (const float4*)(x + (size_t)i * D);
    float4 v[4];
    float ss = 0.0f;
    #pragma unroll
    for (int k = 0; k < 4; k++) {
        v[k] = xr[k];
        ss += v[k].x*v[k].x + v[k].y*v[k].y + v[k].z*v[k].z + v[k].w*v[k].w;
    }
    float inv = 1.0f / fmaxf(sqrtf(ss), 1e-12f);
    float4* o = (float4*)(g_xn + (size_t)i * D);
    #pragma unroll
    for (int k = 0; k < 4; k++) {
        v[k].x*=inv; v[k].y*=inv; v[k].z*=inv; v[k].w*=inv;
        o[k] = v[k];
    }
}

// in-place leaky on x, then write normalized(leaky(x)) to xn (fused inter-layer)
__global__ void k_leaky_norm(float* __restrict__ x, int n) {
    int i = blockIdx.x * blockDim.x + threadIdx.x;
    if (i >= n) return;
    float4* xr = (float4*)(x + (size_t)i * D);
    float4 v[4];
    float ss = 0.0f;
    #pragma unroll
    for (int k = 0; k < 4; k++) {
        v[k] = xr[k];
        v[k].x = leaky(v[k].x); v[k].y = leaky(v[k].y);
        v[k].z = leaky(v[k].z); v[k].w = leaky(v[k].w);
        ss += v[k].x*v[k].x + v[k].y*v[k].y + v[k].z*v[k].z + v[k].w*v[k].w;
        xr[k] = v[k];
    }
    float inv = 1.0f / fmaxf(sqrtf(ss), 1e-12f);
    float4* o = (float4*)(g_xn + (size_t)i * D);
    #pragma unroll
    for (int k = 0; k < 4; k++) {
        v[k].x*=inv; v[k].y*=inv; v[k].z*=inv; v[k].w*=inv;
        o[k] = v[k];
    }
}

// fused: a = exp(beta * dot(xn[s], xn[t])); denom[t] += a
// (segment-max dropped: alpha in [-|beta|,|beta|], softmax shift-invariant)
__global__ void k_edge(const int* __restrict__ es, const int* __restrict__ ed,
                       const float* __restrict__ beta_p, int beta_idx,
                       int n_edges, int e_tot) {
    int e = blockIdx.x * blockDim.x + threadIdx.x;
    if (e >= e_tot) return;
    int s, t; edge_st(e, es, ed, n_edges, s, t);
    const float4* xs = (const float4*)(g_xn + (size_t)s * D);
    const float4* xt = (const float4*)(g_xn + (size_t)t * D);
    float dot = 0.0f;
    #pragma unroll
    for (int k = 0; k < 4; k++) {
        float4 a = xs[k], b = xt[k];
        dot += a.x*b.x + a.y*b.y + a.z*b.z + a.w*b.w;
    }
    float a = expf(__ldg(beta_p + beta_idx) * dot);
    g_alpha[e] = a;
    atomicAdd(&g_denom[t], a);
}

// denom -> 1/(denom + eps) in place
__global__ void k_recip(int n) {
    int i = blockIdx.x * blockDim.x + threadIdx.x;
    if (i < n) g_denom[i] = 1.0f / (g_denom[i] + 1e-16f);
}

// y[t] += (a * dinv[t]) * x[s], one thread per edge, vector reductions
__global__ void k_accum(const int* __restrict__ es, const int* __restrict__ ed,
                        const float* __restrict__ x, float* __restrict__ y,
                        int n_edges, int e_tot) {
    int e = blockIdx.x * blockDim.x + threadIdx.x;
    if (e >= e_tot) return;
    int s, t; edge_st(e, es, ed, n_edges, s, t);
    float w = g_alpha[e] * g_denom[t];
    const float4* xs = (const float4*)(x + (size_t)s * D);
    float* yt = y + (size_t)t * D;
    #pragma unroll
    for (int k = 0; k < 4; k++) {
        float4 v = xs[k];
        asm volatile(
            "red.global.add.v4.f32 [%0], {%1, %2, %3, %4};"
            :: "l"(yt + 4*k), "f"(w*v.x), "f"(w*v.y), "f"(w*v.z), "f"(w*v.w)
            : "memory");
    }
}

// per-row MLP: leaky applied to gathered x2; concat -> 6 -> 16 -> 3
__global__ void k_mlp(const float* __restrict__ x,
                      const int* __restrict__ home, const int* __restrict__ away,
                      const float* __restrict__ w0, const float* __restrict__ b0,
                      const float* __restrict__ w1, const float* __restrict__ b1,
                      const float* __restrict__ w2, const float* __restrict__ b2,
                      float* __restrict__ out, int batch) {
    int i = blockIdx.x * blockDim.x + threadIdx.x;
    if (i >= batch) return;
    float h0[32];
    {
        const float4* hr = (const float4*)(x + (size_t)home[i] * D);
        const float4* ar = (const float4*)(x + (size_t)away[i] * D);
        #pragma unroll
        for (int k = 0; k < 4; k++) {
            float4 v = hr[k];
            h0[4*k+0]=leaky(v.x); h0[4*k+1]=leaky(v.y);
            h0[4*k+2]=leaky(v.z); h0[4*k+3]=leaky(v.w);
        }
        #pragma unroll
        for (int k = 0; k < 4; k++) {
            float4 v = ar[k];
            h0[16+4*k+0]=leaky(v.x); h0[16+4*k+1]=leaky(v.y);
            h0[16+4*k+2]=leaky(v.z); h0[16+4*k+3]=leaky(v.w);
        }
    }
    float h1[6];
    #pragma unroll
    for (int j = 0; j < 6; j++) {
        float acc = __ldg(b0 + j);
        #pragma unroll
        for (int k = 0; k < 32; k++) acc += h0[k] * __ldg(w0 + k*6 + j);
        h1[j] = leaky(acc);
    }
    float h2[16];
    #pragma unroll
    for (int j = 0; j < 16; j++) {
        float acc = __ldg(b1 + j);
        #pragma unroll
        for (int k = 0; k < 6; k++) acc += h1[k] * __ldg(w1 + k*16 + j);
        h2[j] = leaky(acc);
    }
    #pragma unroll
    for (int j = 0; j < 3; j++) {
        float acc = __ldg(b2 + j);
        #pragma unroll
        for (int k = 0; k < 16; k++) acc += h2[k] * __ldg(w2 + k*3 + j);
        out[(size_t)i * 3 + j] = leaky(acc);
    }
}

// one pass: per-block max then sum(exp(v - blockmax)) for each of 3 columns
__global__ void k_colstats(const float* __restrict__ h, int batch) {
    __shared__ float sred[3][8];
    __shared__ float sbm[3];
    int w = threadIdx.x >> 5, l = threadIdx.x & 31;

    float lm[3] = {-INFINITY, -INFINITY, -INFINITY};
    for (int i = blockIdx.x * blockDim.x + threadIdx.x; i < batch;
         i += gridDim.x * blockDim.x) {
        lm[0] = fmaxf(lm[0], h[(size_t)i*3+0]);
        lm[1] = fmaxf(lm[1], h[(size_t)i*3+1]);
        lm[2] = fmaxf(lm[2], h[(size_t)i*3+2]);
    }
    #pragma unroll
    for (int j = 0; j < 3; j++) {
        float v = warpMax(lm[j]);
        if (l == 0) sred[j][w] = v;
    }
    __syncthreads();
    if (threadIdx.x < 3) {
        float v = sred[threadIdx.x][0];
        #pragma unroll
        for (int k = 1; k < 8; k++) v = fmaxf(v, sred[threadIdx.x][k]);
        sbm[threadIdx.x] = v;
    }
    __syncthreads();
    float bm0 = sbm[0], bm1 = sbm[1], bm2 = sbm[2];

    float ls[3] = {0.0f, 0.0f, 0.0f};
    for (int i = blockIdx.x * blockDim.x + threadIdx.x; i < batch;
         i += gridDim.x * blockDim.x) {
        ls[0] += __expf(h[(size_t)i*3+0] - bm0);
        ls[1] += __expf(h[(size_t)i*3+1] - bm1);
        ls[2] += __expf(h[(size_t)i*3+2] - bm2);
    }
    __syncthreads();
    #pragma unroll
    for (int j = 0; j < 3; j++) {
        float v = warpSum(ls[j]);
        if (l == 0) sred[j][w] = v;
    }
    __syncthreads();
    if (threadIdx.x < 3) {
        float v = 0.0f;
        #pragma unroll
        for (int k = 0; k < 8; k++) v += sred[threadIdx.x][k];
        g_bmax[blockIdx.x * 3 + threadIdx.x] = sbm[threadIdx.x];
        g_bsum[blockIdx.x * 3 + threadIdx.x] = v;
    }
}

// combine CSB blocks' (max, sum) -> g_cls[j] = colmax + log(colsum); 3 warps
__global__ void k_colfix() {
    int j = threadIdx.x >> 5;   // col (0..2)
    int l = threadIdx.x & 31;
    if (j >= 3) return;
    float m = -INFINITY;
    for (int b = l; b < CSB; b += 32) m = fmaxf(m, g_bmax[b*3 + j]);
    m = warpMax(m);
    float s = 0.0f;
    for (int b = l; b < CSB; b += 32)
        s += g_bsum[b*3 + j] * __expf(g_bmax[b*3 + j] - m);
    s = warpSum(s);
    if (l == 0) g_cls[j] = m + logf(s);
}

__global__ void k_final(float* __restrict__ out, int batch) {
    int i = blockIdx.x * blockDim.x + threadIdx.x;
    if (i >= batch * 3) return;
    out[i] -= g_cls[i % 3];
}

// ---------------- launch ----------------------------------------------------
extern "C" void kernel_launch(void* const* d_in, const int* in_sizes, int n_in,
                              void* d_out, int out_size) {
    const float* embed  = (const float*)d_in[0];
    const float* beta   = (const float*)d_in[1];
    const float* w0     = (const float*)d_in[2];
    const float* b0     = (const float*)d_in[3];
    const float* w1     = (const float*)d_in[4];
    const float* b1     = (const float*)d_in[5];
    const float* w2     = (const float*)d_in[6];
    const float* b2     = (const float*)d_in[7];
    const int*   eidx   = (const int*)d_in[8];
    const int*   home   = (const int*)d_in[9];
    const int*   away   = (const int*)d_in[10];
    float* out = (float*)d_out;

    const int n      = in_sizes[0] / D;          // 200000
    const int nedges = in_sizes[8] / 2;          // 3200000
    const int etot   = nedges + n;
    const int batch  = in_sizes[9];              // 500000

    const int* es = eidx;            // row 0: src
    const int* ed = eidx + nedges;   // row 1: dst

    float* x1; cudaGetSymbolAddress((void**)&x1, g_x1);
    float* x2; cudaGetSymbolAddress((void**)&x2, g_x2);

    const int TB = 256;
    int gN   = (n + TB - 1) / TB;
    int gND  = (n * D + TB - 1) / TB;
    int gE   = (etot + TB - 1) / TB;
    int gB   = (batch + TB - 1) / TB;
    int gB3  = (batch * 3 + TB - 1) / TB;

    // ---- layer 1 (input = embed) ----
    k_init<<<gND, TB>>>(x1, n);
    k_normalize<<<gN, TB>>>(embed, n);
    k_edge<<<gE, TB>>>(es, ed, beta, 0, nedges, etot);
    k_recip<<<gN, TB>>>(n);
    k_accum<<<gE, TB>>>(es, ed, embed, x1, nedges, etot);

    // ---- layer 2 (input = leaky(x1)) ----
    k_init<<<gND, TB>>>(x2, n);
    k_leaky_norm<<<gN, TB>>>(x1, n);
    k_edge<<<gE, TB>>>(es, ed, beta, 1, nedges, etot);
    k_recip<<<gN, TB>>>(n);
    k_accum<<<gE, TB>>>(es, ed, x1, x2, nedges, etot);

    // ---- MLP (leaky(x2) fused into gather) + log_softmax(dim=0) ----
    k_mlp<<<gB, TB>>>(x2, home, away, w0, b0, w1, b1, w2, b2, out, batch);
    k_colstats<<<CSB, TB>>>(out, batch);
    k_colfix<<<1, 96>>>();
    k_final<<<gB3, TB>>>(out, batch);
}

// round 3
// speedup vs baseline: 1.6699x; 1.1400x over previous
#include <cuda_runtime.h>
#include <math.h>
#include <stdint.h>

#define N_TEAMS 200000
#define D 16
#define N_EDGES 3200000
#define E_TOT (N_EDGES + N_TEAMS)
#define NEG_SLOPE 0.01f
#define MAXB 4096
#define SCAN_BLK 1024

// ---------------- scratch (device globals) ----------------------------------
__device__ float g_xn[N_TEAMS * D];     // normalized features of current layer input
__device__ float g_norm[N_TEAMS];       // ||x|| per node (clamped)
__device__ float g_x1[N_TEAMS * D];     // layer1 output (leaky applied)
__device__ float g_x2[N_TEAMS * D];     // layer2 output (leaky applied)
__device__ int   g_deg[N_TEAMS];
__device__ int   g_off[N_TEAMS + 1];
__device__ int   g_cur[N_TEAMS];
__device__ int   g_csr_src[E_TOT];
__device__ int   g_bsums[(N_TEAMS + SCAN_BLK - 1) / SCAN_BLK];
__device__ float g_bmax[MAXB * 3];
__device__ float g_bsum[MAXB * 3];
__device__ float g_cls[3];

// ---------------- helpers ----------------------------------------------------
__device__ __forceinline__ float leaky(float v) {
    return v > 0.0f ? v : NEG_SLOPE * v;
}
__device__ __forceinline__ float warpMax(float v) {
    #pragma unroll
    for (int o = 16; o; o >>= 1) v = fmaxf(v, __shfl_xor_sync(0xffffffffu, v, o));
    return v;
}
__device__ __forceinline__ float warpSum(float v) {
    #pragma unroll
    for (int o = 16; o; o >>= 1) v += __shfl_xor_sync(0xffffffffu, v, o);
    return v;
}
__device__ __forceinline__ void edge_st(int e, const int* __restrict__ es,
                                        const int* __restrict__ ed,
                                        int n_edges, int& s, int& t) {
    if (e < n_edges) { s = es[e]; t = ed[e]; }
    else             { s = t = e - n_edges; }
}

// ---------------- CSR build --------------------------------------------------
__global__ void k_zero_deg(int n) {
    int i = blockIdx.x * blockDim.x + threadIdx.x;
    if (i < n) g_deg[i] = 0;
}

__global__ void k_count(const int* __restrict__ es, const int* __restrict__ ed,
                        int n_edges, int e_tot) {
    int e = blockIdx.x * blockDim.x + threadIdx.x;
    if (e >= e_tot) return;
    int s, t; edge_st(e, es, ed, n_edges, s, t);
    (void)s;
    atomicAdd(&g_deg[t], 1);
}

__global__ void k_scan1(int n) {
    __shared__ int sh[SCAN_BLK];
    int i = blockIdx.x * SCAN_BLK + threadIdx.x;
    int v = (i < n) ? g_deg[i] : 0;
    sh[threadIdx.x] = v;
    __syncthreads();
    #pragma unroll
    for (int ofs = 1; ofs < SCAN_BLK; ofs <<= 1) {
        int t = (threadIdx.x >= ofs) ? sh[threadIdx.x - ofs] : 0;
        __syncthreads();
        sh[threadIdx.x] += t;
        __syncthreads();
    }
    if (i < n) g_off[i] = sh[threadIdx.x] - v;       // exclusive
    if (threadIdx.x == SCAN_BLK - 1) g_bsums[blockIdx.x] = sh[threadIdx.x];
}

__global__ void k_scan2(int nb) {
    __shared__ int sh[SCAN_BLK];
    int v = (threadIdx.x < nb) ? g_bsums[threadIdx.x] : 0;
    sh[threadIdx.x] = v;
    __syncthreads();
    #pragma unroll
    for (int ofs = 1; ofs < SCAN_BLK; ofs <<= 1) {
        int t = (threadIdx.x >= ofs) ? sh[threadIdx.x - ofs] : 0;
        __syncthreads();
        sh[threadIdx.x] += t;
        __syncthreads();
    }
    if (threadIdx.x < nb) g_bsums[threadIdx.x] = sh[threadIdx.x] - v;  // exclusive
}

__global__ void k_scan3(int n, int e_tot) {
    int i = blockIdx.x * blockDim.x + threadIdx.x;
    if (i < n) {
        int o = g_off[i] + g_bsums[i / SCAN_BLK];
        g_off[i] = o;
        g_cur[i] = o;
    }
    if (i == 0) g_off[n] = e_tot;
}

__global__ void k_scatter(const int* __restrict__ es, const int* __restrict__ ed,
                          int n_edges, int e_tot) {
    int e = blockIdx.x * blockDim.x + threadIdx.x;
    if (e >= e_tot) return;
    int s, t; edge_st(e, es, ed, n_edges, s, t);
    int pos = atomicAdd(&g_cur[t], 1);
    g_csr_src[pos] = s;
}

// ---------------- node normalize (layer-1 prologue) -------------------------
__global__ void k_norm0(const float* __restrict__ x, int n) {
    int i = blockIdx.x * blockDim.x + threadIdx.x;
    if (i >= n) return;
    const float4* xr = (const float4*)(x + (size_t)i * D);
    float4 v[4];
    float ss = 0.0f;
    #pragma unroll
    for (int k = 0; k < 4; k++) {
        v[k] = xr[k];
        ss += v[k].x*v[k].x + v[k].y*v[k].y + v[k].z*v[k].z + v[k].w*v[k].w;
    }
    float nm = fmaxf(sqrtf(ss), 1e-12f);
    float inv = 1.0f / nm;
    g_norm[i] = nm;
    float4* o = (float4*)(g_xn + (size_t)i * D);
    #pragma unroll
    for (int k = 0; k < 4; k++) {
        v[k].x*=inv; v[k].y*=inv; v[k].z*=inv; v[k].w*=inv;
        o[k] = v[k];
    }
}

// ---------------- AGNN layer: warp per dst, gather-only, no atomics ---------
// out[dst] = leaky( sum_e softmax(beta*dot(xn_s,xn_d)) * norm[s]*xn[s] )
// If WRITE_NORM: also refresh g_xn/g_norm from the leaky output (for next layer).
template <int WRITE_NORM>
__global__ void __launch_bounds__(256)
k_layer(const float* __restrict__ beta_p, int beta_idx,
        float* __restrict__ y, int n) {
    int wid = (blockIdx.x * blockDim.x + threadIdx.x) >> 5;
    int lane = threadIdx.x & 31;
    if (wid >= n) return;
    int dst = wid;

    const float4* pd = (const float4*)(g_xn + (size_t)dst * D);
    float4 d0 = pd[0], d1 = pd[1], d2 = pd[2], d3 = pd[3];

    int beg = g_off[dst], end = g_off[dst + 1];
    float beta = __ldg(beta_p + beta_idx);

    float denom = 0.0f;
    float4 a0 = {0,0,0,0}, a1 = {0,0,0,0}, a2 = {0,0,0,0}, a3 = {0,0,0,0};

    for (int e = beg + lane; e < end; e += 32) {
        int s = g_csr_src[e];
        const float4* ps = (const float4*)(g_xn + (size_t)s * D);
        float4 s0 = ps[0], s1 = ps[1], s2 = ps[2], s3 = ps[3];
        float dot = s0.x*d0.x + s0.y*d0.y + s0.z*d0.z + s0.w*d0.w
                  + s1.x*d1.x + s1.y*d1.y + s1.z*d1.z + s1.w*d1.w
                  + s2.x*d2.x + s2.y*d2.y + s2.z*d2.z + s2.w*d2.w
                  + s3.x*d3.x + s3.y*d3.y + s3.z*d3.z + s3.w*d3.w;
        float a = expf(beta * dot);
        denom += a;
        float w = a * g_norm[s];
        a0.x += w*s0.x; a0.y += w*s0.y; a0.z += w*s0.z; a0.w += w*s0.w;
        a1.x += w*s1.x; a1.y += w*s1.y; a1.z += w*s1.z; a1.w += w*s1.w;
        a2.x += w*s2.x; a2.y += w*s2.y; a2.z += w*s2.z; a2.w += w*s2.w;
        a3.x += w*s3.x; a3.y += w*s3.y; a3.z += w*s3.z; a3.w += w*s3.w;
    }

    denom = warpSum(denom);
    a0.x = warpSum(a0.x); a0.y = warpSum(a0.y); a0.z = warpSum(a0.z); a0.w = warpSum(a0.w);
    a1.x = warpSum(a1.x); a1.y = warpSum(a1.y); a1.z = warpSum(a1.z); a1.w = warpSum(a1.w);
    a2.x = warpSum(a2.x); a2.y = warpSum(a2.y); a2.z = warpSum(a2.z); a2.w = warpSum(a2.w);
    a3.x = warpSum(a3.x); a3.y = warpSum(a3.y); a3.z = warpSum(a3.z); a3.w = warpSum(a3.w);

    if (lane == 0) {
        float inv = 1.0f / (denom + 1e-16f);
        // leaky applied here (fused activation)
        a0.x = leaky(a0.x*inv); a0.y = leaky(a0.y*inv); a0.z = leaky(a0.z*inv); a0.w = leaky(a0.w*inv);
        a1.x = leaky(a1.x*inv); a1.y = leaky(a1.y*inv); a1.z = leaky(a1.z*inv); a1.w = leaky(a1.w*inv);
        a2.x = leaky(a2.x*inv); a2.y = leaky(a2.y*inv); a2.z = leaky(a2.z*inv); a2.w = leaky(a2.w*inv);
        a3.x = leaky(a3.x*inv); a3.y = leaky(a3.y*inv); a3.z = leaky(a3.z*inv); a3.w = leaky(a3.w*inv);
        float4* o = (float4*)(y + (size_t)dst * D);
        o[0] = a0; o[1] = a1; o[2] = a2; o[3] = a3;
        if (WRITE_NORM) {
            float ss = a0.x*a0.x + a0.y*a0.y + a0.z*a0.z + a0.w*a0.w
                     + a1.x*a1.x + a1.y*a1.y + a1.z*a1.z + a1.w*a1.w
                     + a2.x*a2.x + a2.y*a2.y + a2.z*a2.z + a2.w*a2.w
                     + a3.x*a3.x + a3.y*a3.y + a3.z*a3.z + a3.w*a3.w;
            float nm = fmaxf(sqrtf(ss), 1e-12f);
            float ninv = 1.0f / nm;
            g_norm[dst] = nm;
            float4* xo = (float4*)(g_xn + (size_t)dst * D);
            float4 b0=a0,b1=a1,b2=a2,b3=a3;
            b0.x*=ninv; b0.y*=ninv; b0.z*=ninv; b0.w*=ninv;
            b1.x*=ninv; b1.y*=ninv; b1.z*=ninv; b1.w*=ninv;
            b2.x*=ninv; b2.y*=ninv; b2.z*=ninv; b2.w*=ninv;
            b3.x*=ninv; b3.y*=ninv; b3.z*=ninv; b3.w*=ninv;
            xo[0]=b0; xo[1]=b1; xo[2]=b2; xo[3]=b3;
        }
    }
}

// ---------------- MLP + fused per-block column stats -------------------------
__global__ void k_mlp_stats(const float* __restrict__ x,
                            const int* __restrict__ home, const int* __restrict__ away,
                            const float* __restrict__ w0, const float* __restrict__ b0,
                            const float* __restrict__ w1, const float* __restrict__ b1,
                            const float* __restrict__ w2, const float* __restrict__ b2,
                            float* __restrict__ out, int batch) {
    int i = blockIdx.x * blockDim.x + threadIdx.x;
    float v[3] = {-INFINITY, -INFINITY, -INFINITY};
    if (i < batch) {
        float h0[32];
        const float4* hr = (const float4*)(x + (size_t)home[i] * D);
        const float4* ar = (const float4*)(x + (size_t)away[i] * D);
        #pragma unroll
        for (int k = 0; k < 4; k++) {
            float4 q = hr[k];
            h0[4*k+0]=q.x; h0[4*k+1]=q.y; h0[4*k+2]=q.z; h0[4*k+3]=q.w;
        }
        #pragma unroll
        for (int k = 0; k < 4; k++) {
            float4 q = ar[k];
            h0[16+4*k+0]=q.x; h0[16+4*k+1]=q.y; h0[16+4*k+2]=q.z; h0[16+4*k+3]=q.w;
        }
        float h1[6];
        #pragma unroll
        for (int j = 0; j < 6; j++) {
            float acc = __ldg(b0 + j);
            #pragma unroll
            for (int k = 0; k < 32; k++) acc += h0[k] * __ldg(w0 + k*6 + j);
            h1[j] = leaky(acc);
        }
        float h2[16];
        #pragma unroll
        for (int j = 0; j < 16; j++) {
            float acc = __ldg(b1 + j);
            #pragma unroll
            for (int k = 0; k < 6; k++) acc += h1[k] * __ldg(w1 + k*16 + j);
            h2[j] = leaky(acc);
        }
        #pragma unroll
        for (int j = 0; j < 3; j++) {
            float acc = __ldg(b2 + j);
            #pragma unroll
            for (int k = 0; k < 16; k++) acc += h2[k] * __ldg(w2 + k*3 + j);
            v[j] = leaky(acc);
            out[(size_t)i * 3 + j] = v[j];
        }
    }

    // fused block stats: max then sum(exp(v - blockmax)) per column
    __shared__ float sred[3][8];
    __shared__ float sbm[3];
    int w = threadIdx.x >> 5, l = threadIdx.x & 31;
    #pragma unroll
    for (int j = 0; j < 3; j++) {
        float m = warpMax(v[j]);
        if (l == 0) sred[j][w] = m;
    }
    __syncthreads();
    if (threadIdx.x < 3) {
        float m = sred[threadIdx.x][0];
        #pragma unroll
        for (int k = 1; k < 8; k++) m = fmaxf(m, sred[threadIdx.x][k]);
        sbm[threadIdx.x] = m;
    }
    __syncthreads();
    float e0 = (i < batch) ? __expf(v[0] - sbm[0]) : 0.0f;
    float e1 = (i < batch) ? __expf(v[1] - sbm[1]) : 0.0f;
    float e2 = (i < batch) ? __expf(v[2] - sbm[2]) : 0.0f;
    float es_[3] = {e0, e1, e2};
    __syncthreads();
    #pragma unroll
    for (int j = 0; j < 3; j++) {
        float s = warpSum(es_[j]);
        if (l == 0) sred[j][w] = s;
    }
    __syncthreads();
    if (threadIdx.x < 3) {
        float s = 0.0f;
        #pragma unroll
        for (int k = 0; k < 8; k++) s += sred[threadIdx.x][k];
        g_bmax[blockIdx.x * 3 + threadIdx.x] = sbm[threadIdx.x];
        g_bsum[blockIdx.x * 3 + threadIdx.x] = s;
    }
}

// combine nb blocks' (max, sum): g_cls[j] = colmax + log(colsum)
__global__ void k_colfix(int nb) {
    int j = threadIdx.x >> 5;
    int l = threadIdx.x & 31;
    if (j >= 3) return;
    float m = -INFINITY;
    for (int b = l; b < nb; b += 32) m = fmaxf(m, g_bmax[b*3 + j]);
    m = warpMax(m);
    float s = 0.0f;
    for (int b = l; b < nb; b += 32)
        s += g_bsum[b*3 + j] * __expf(g_bmax[b*3 + j] - m);
    s = warpSum(s);
    if (l == 0) g_cls[j] = m + logf(s);
}

__global__ void k_final(float* __restrict__ out, int batch) {
    int i = blockIdx.x * blockDim.x + threadIdx.x;
    if (i >= batch * 3) return;
    out[i] -= g_cls[i % 3];
}

// ---------------- launch ------------------------------------------------------
extern "C" void kernel_launch(void* const* d_in, const int* in_sizes, int n_in,
                              void* d_out, int out_size) {
    const float* embed  = (const float*)d_in[0];
    const float* beta   = (const float*)d_in[1];
    const float* w0     = (const float*)d_in[2];
    const float* b0     = (const float*)d_in[3];
    const float* w1     = (const float*)d_in[4];
    const float* b1     = (const float*)d_in[5];
    const float* w2     = (const float*)d_in[6];
    const float* b2     = (const float*)d_in[7];
    const int*   eidx   = (const int*)d_in[8];
    const int*   home   = (const int*)d_in[9];
    const int*   away   = (const int*)d_in[10];
    float* out = (float*)d_out;

    const int n      = in_sizes[0] / D;          // 200000
    const int nedges = in_sizes[8] / 2;          // 3200000
    const int etot   = nedges + n;
    const int batch  = in_sizes[9];              // 500000

    const int* es = eidx;
    const int* ed = eidx + nedges;

    float* x1; cudaGetSymbolAddress((void**)&x1, g_x1);
    float* x2; cudaGetSymbolAddress((void**)&x2, g_x2);

    const int TB = 256;
    int gN   = (n + TB - 1) / TB;
    int gE   = (etot + TB - 1) / TB;
    int gB   = (batch + TB - 1) / TB;
    int gB3  = (batch * 3 + TB - 1) / TB;
    int gW   = (n * 32 + TB - 1) / TB;           // warp per dst
    int nsb  = (n + SCAN_BLK - 1) / SCAN_BLK;    // scan blocks (196)

    // ---- CSR build (shared by both layers) ----
    k_zero_deg<<<gN, TB>>>(n);
    k_count<<<gE, TB>>>(es, ed, nedges, etot);
    k_scan1<<<nsb, SCAN_BLK>>>(n);
    k_scan2<<<1, SCAN_BLK>>>(nsb);
    k_scan3<<<gN, TB>>>(n, etot);
    k_scatter<<<gE, TB>>>(es, ed, nedges, etot);

    // ---- layer 1 (input = embed) ----
    k_norm0<<<gN, TB>>>(embed, n);
    k_layer<1><<<gW, TB>>>(beta, 0, x1, n);      // writes leaky(x1), refreshes xn/norm

    // ---- layer 2 ----
    k_layer<0><<<gW, TB>>>(beta, 1, x2, n);      // writes leaky(x2)

    // ---- MLP + log_softmax(dim=0) ----
    k_mlp_stats<<<gB, TB>>>(x2, home, away, w0, b0, w1, b1, w2, b2, out, batch);
    k_colfix<<<1, 96>>>(gB);
    k_final<<<gB3, TB>>>(out, batch);
}

// round 4
// speedup vs baseline: 2.1278x; 1.2742x over previous
#include <cuda_runtime.h>
#include <math.h>
#include <stdint.h>

#define N_TEAMS 200000
#define D 16
#define N_EDGES 3200000
#define E_TOT (N_EDGES + N_TEAMS)
#define NEG_SLOPE 0.01f
#define MAXB 4096
#define SCAN_BLK 1024

// ---------------- scratch (device globals) ----------------------------------
__device__ float g_xn[N_TEAMS * D];     // normalized features of current layer input
__device__ float g_norm[N_TEAMS];       // ||x|| per node (clamped)
__device__ float g_x1[N_TEAMS * D];     // layer1 output (leaky applied)
__device__ float g_x2[N_TEAMS * D];     // layer2 output (leaky applied)
__device__ int   g_deg[N_TEAMS];
__device__ int   g_off[N_TEAMS + 1];
__device__ int   g_cur[N_TEAMS];
__device__ int   g_csr_src[E_TOT];
__device__ int   g_bsums[(N_TEAMS + SCAN_BLK - 1) / SCAN_BLK];
__device__ float g_bmax[MAXB * 3];
__device__ float g_bsum[MAXB * 3];
__device__ float g_cls[3];

// ---------------- helpers ----------------------------------------------------
__device__ __forceinline__ float leaky(float v) {
    return v > 0.0f ? v : NEG_SLOPE * v;
}
__device__ __forceinline__ float warpMax(float v) {
    #pragma unroll
    for (int o = 16; o; o >>= 1) v = fmaxf(v, __shfl_xor_sync(0xffffffffu, v, o));
    return v;
}
__device__ __forceinline__ float warpSum(float v) {
    #pragma unroll
    for (int o = 16; o; o >>= 1) v += __shfl_xor_sync(0xffffffffu, v, o);
    return v;
}
__device__ __forceinline__ void edge_st(int e, const int* __restrict__ es,
                                        const int* __restrict__ ed,
                                        int n_edges, int& s, int& t) {
    if (e < n_edges) { s = es[e]; t = ed[e]; }
    else             { s = t = e - n_edges; }
}

// ---------------- CSR build --------------------------------------------------
__global__ void k_zero_deg(int n) {
    int i = blockIdx.x * blockDim.x + threadIdx.x;
    if (i < n) g_deg[i] = 0;
}

__global__ void k_count(const int* __restrict__ es, const int* __restrict__ ed,
                        int n_edges, int e_tot) {
    int e = blockIdx.x * blockDim.x + threadIdx.x;
    if (e >= e_tot) return;
    int s, t; edge_st(e, es, ed, n_edges, s, t);
    (void)s;
    atomicAdd(&g_deg[t], 1);
}

__global__ void k_scan1(int n) {
    __shared__ int sh[SCAN_BLK];
    int i = blockIdx.x * SCAN_BLK + threadIdx.x;
    int v = (i < n) ? g_deg[i] : 0;
    sh[threadIdx.x] = v;
    __syncthreads();
    #pragma unroll
    for (int ofs = 1; ofs < SCAN_BLK; ofs <<= 1) {
        int t = (threadIdx.x >= ofs) ? sh[threadIdx.x - ofs] : 0;
        __syncthreads();
        sh[threadIdx.x] += t;
        __syncthreads();
    }
    if (i < n) g_off[i] = sh[threadIdx.x] - v;       // exclusive
    if (threadIdx.x == SCAN_BLK - 1) g_bsums[blockIdx.x] = sh[threadIdx.x];
}

__global__ void k_scan2(int nb) {
    __shared__ int sh[SCAN_BLK];
    int v = (threadIdx.x < nb) ? g_bsums[threadIdx.x] : 0;
    sh[threadIdx.x] = v;
    __syncthreads();
    #pragma unroll
    for (int ofs = 1; ofs < SCAN_BLK; ofs <<= 1) {
        int t = (threadIdx.x >= ofs) ? sh[threadIdx.x - ofs] : 0;
        __syncthreads();
        sh[threadIdx.x] += t;
        __syncthreads();
    }
    if (threadIdx.x < nb) g_bsums[threadIdx.x] = sh[threadIdx.x] - v;  // exclusive
}

__global__ void k_scan3(int n, int e_tot) {
    int i = blockIdx.x * blockDim.x + threadIdx.x;
    if (i < n) {
        int o = g_off[i] + g_bsums[i / SCAN_BLK];
        g_off[i] = o;
        g_cur[i] = o;
    }
    if (i == 0) g_off[n] = e_tot;
}

__global__ void k_scatter(const int* __restrict__ es, const int* __restrict__ ed,
                          int n_edges, int e_tot) {
    int e = blockIdx.x * blockDim.x + threadIdx.x;
    if (e >= e_tot) return;
    int s, t; edge_st(e, es, ed, n_edges, s, t);
    int pos = atomicAdd(&g_cur[t], 1);
    g_csr_src[pos] = s;
}

// ---------------- node normalize (layer-1 prologue) -------------------------
__global__ void k_norm0(const float* __restrict__ x, int n) {
    int i = blockIdx.x * blockDim.x + threadIdx.x;
    if (i >= n) return;
    const float4* xr = (const float4*)(x + (size_t)i * D);
    float4 v[4];
    float ss = 0.0f;
    #pragma unroll
    for (int k = 0; k < 4; k++) {
        v[k] = xr[k];
        ss += v[k].x*v[k].x + v[k].y*v[k].y + v[k].z*v[k].z + v[k].w*v[k].w;
    }
    float nm = fmaxf(sqrtf(ss), 1e-12f);
    float inv = 1.0f / nm;
    g_norm[i] = nm;
    float4* o = (float4*)(g_xn + (size_t)i * D);
    #pragma unroll
    for (int k = 0; k < 4; k++) {
        v[k].x*=inv; v[k].y*=inv; v[k].z*=inv; v[k].w*=inv;
        o[k] = v[k];
    }
}

// ---------------- AGNN layer: warp per dst, 4 lanes cooperate per edge ------
// Lane = (group g=lane>>2, quarter r=lane&3). Group handles one edge at a
// time; each lane loads one float4 of the src row (8 lines/LDG instead of 32).
template <int WRITE_NORM>
__global__ void __launch_bounds__(256)
k_layer(const float* __restrict__ beta_p, int beta_idx,
        float* __restrict__ y, int n) {
    int warp = (blockIdx.x * blockDim.x + threadIdx.x) >> 5;
    if (warp >= n) return;
    int lane = threadIdx.x & 31;
    int g = lane >> 2, r = lane & 3;
    int dst = warp;

    float4 d4 = __ldg((const float4*)(g_xn + (size_t)dst * D) + r);
    int beg = g_off[dst], end = g_off[dst + 1];
    float beta = __ldg(beta_p + beta_idx);

    float denom = 0.0f;
    float4 acc = {0, 0, 0, 0};
    int nIter = (end - beg + 7) >> 3;

    for (int k = 0; k < nIter; k++) {
        int e = beg + (k << 3) + g;
        bool act = (e < end);
        int s = act ? __ldg(g_csr_src + e) : dst;
        float4 v = __ldg((const float4*)(g_xn + (size_t)s * D) + r);
        float pd = v.x*d4.x + v.y*d4.y + v.z*d4.z + v.w*d4.w;
        pd += __shfl_xor_sync(0xffffffffu, pd, 1);
        pd += __shfl_xor_sync(0xffffffffu, pd, 2);
        float a = act ? expf(beta * pd) : 0.0f;
        denom += a;
        float w = a * __ldg(g_norm + s);
        acc.x += w*v.x; acc.y += w*v.y; acc.z += w*v.z; acc.w += w*v.w;
    }

    // reduce across the 8 groups (lanes keep their quarter r)
    #pragma unroll
    for (int ofs = 4; ofs < 32; ofs <<= 1) {
        acc.x += __shfl_xor_sync(0xffffffffu, acc.x, ofs);
        acc.y += __shfl_xor_sync(0xffffffffu, acc.y, ofs);
        acc.z += __shfl_xor_sync(0xffffffffu, acc.z, ofs);
        acc.w += __shfl_xor_sync(0xffffffffu, acc.w, ofs);
        denom += __shfl_xor_sync(0xffffffffu, denom, ofs);
    }
    // lanes 0..3 now hold full quarter-sums; denom is complete in each.

    if (g == 0) {
        float inv = 1.0f / (denom + 1e-16f);
        acc.x = leaky(acc.x * inv); acc.y = leaky(acc.y * inv);
        acc.z = leaky(acc.z * inv); acc.w = leaky(acc.w * inv);
        ((float4*)(y + (size_t)dst * D))[r] = acc;   // 4 lanes -> 64B coalesced
        if (WRITE_NORM) {
            float ssq = acc.x*acc.x + acc.y*acc.y + acc.z*acc.z + acc.w*acc.w;
            ssq += __shfl_xor_sync(0x0000000Fu, ssq, 1);
            ssq += __shfl_xor_sync(0x0000000Fu, ssq, 2);
            float nm = fmaxf(sqrtf(ssq), 1e-12f);
            float ninv = 1.0f / nm;
            if (r == 0) g_norm[dst] = nm;
            float4 b = {acc.x*ninv, acc.y*ninv, acc.z*ninv, acc.w*ninv};
            ((float4*)(g_xn + (size_t)dst * D))[r] = b;
        }
    }
}

// ---------------- MLP (smem weights) + fused per-block column stats ----------
__global__ void k_mlp_stats(const float* __restrict__ x,
                            const int* __restrict__ home, const int* __restrict__ away,
                            const float* __restrict__ w0, const float* __restrict__ b0,
                            const float* __restrict__ w1, const float* __restrict__ b1,
                            const float* __restrict__ w2, const float* __restrict__ b2,
                            float* __restrict__ out, int batch) {
    __shared__ float sw0[192], sw1[96], sw2[48], sb0[6], sb1[16], sb2[3];
    {
        int t = threadIdx.x;
        if (t < 192) sw0[t] = w0[t];
        if (t < 96)  sw1[t] = w1[t];
        if (t < 48)  sw2[t] = w2[t];
        if (t < 16)  sb1[t] = b1[t];
        if (t < 6)   sb0[t] = b0[t];
        if (t < 3)   sb2[t] = b2[t];
    }
    __syncthreads();

    int i = blockIdx.x * blockDim.x + threadIdx.x;
    float v[3] = {-INFINITY, -INFINITY, -INFINITY};
    if (i < batch) {
        float h0[32];
        const float4* hr = (const float4*)(x + (size_t)home[i] * D);
        const float4* ar = (const float4*)(x + (size_t)away[i] * D);
        #pragma unroll
        for (int k = 0; k < 4; k++) {
            float4 q = __ldg(hr + k);
            h0[4*k+0]=q.x; h0[4*k+1]=q.y; h0[4*k+2]=q.z; h0[4*k+3]=q.w;
        }
        #pragma unroll
        for (int k = 0; k < 4; k++) {
            float4 q = __ldg(ar + k);
            h0[16+4*k+0]=q.x; h0[16+4*k+1]=q.y; h0[16+4*k+2]=q.z; h0[16+4*k+3]=q.w;
        }
        float h1[6];
        #pragma unroll
        for (int j = 0; j < 6; j++) {
            float acc = sb0[j];
            #pragma unroll
            for (int k = 0; k < 32; k++) acc += h0[k] * sw0[k*6 + j];
            h1[j] = leaky(acc);
        }
        float h2[16];
        #pragma unroll
        for (int j = 0; j < 16; j++) {
            float acc = sb1[j];
            #pragma unroll
            for (int k = 0; k < 6; k++) acc += h1[k] * sw1[k*16 + j];
            h2[j] = leaky(acc);
        }
        #pragma unroll
        for (int j = 0; j < 3; j++) {
            float acc = sb2[j];
            #pragma unroll
            for (int k = 0; k < 16; k++) acc += h2[k] * sw2[k*3 + j];
            v[j] = leaky(acc);
            out[(size_t)i * 3 + j] = v[j];
        }
    }

    // fused block stats: max then sum(exp(v - blockmax)) per column
    __shared__ float sred[3][8];
    __shared__ float sbm[3];
    int w = threadIdx.x >> 5, l = threadIdx.x & 31;
    #pragma unroll
    for (int j = 0; j < 3; j++) {
        float m = warpMax(v[j]);
        if (l == 0) sred[j][w] = m;
    }
    __syncthreads();
    if (threadIdx.x < 3) {
        float m = sred[threadIdx.x][0];
        #pragma unroll
        for (int k = 1; k < 8; k++) m = fmaxf(m, sred[threadIdx.x][k]);
        sbm[threadIdx.x] = m;
    }
    __syncthreads();
    float es_[3];
    es_[0] = (i < batch) ? __expf(v[0] - sbm[0]) : 0.0f;
    es_[1] = (i < batch) ? __expf(v[1] - sbm[1]) : 0.0f;
    es_[2] = (i < batch) ? __expf(v[2] - sbm[2]) : 0.0f;
    __syncthreads();
    #pragma unroll
    for (int j = 0; j < 3; j++) {
        float s = warpSum(es_[j]);
        if (l == 0) sred[j][w] = s;
    }
    __syncthreads();
    if (threadIdx.x < 3) {
        float s = 0.0f;
        #pragma unroll
        for (int k = 0; k < 8; k++) s += sred[threadIdx.x][k];
        g_bmax[blockIdx.x * 3 + threadIdx.x] = sbm[threadIdx.x];
        g_bsum[blockIdx.x * 3 + threadIdx.x] = s;
    }
}

// combine nb blocks' (max, sum): g_cls[j] = colmax + log(colsum)
__global__ void k_colfix(int nb) {
    int j = threadIdx.x >> 5;
    int l = threadIdx.x & 31;
    if (j >= 3) return;
    float m = -INFINITY;
    for (int b = l; b < nb; b += 32) m = fmaxf(m, g_bmax[b*3 + j]);
    m = warpMax(m);
    float s = 0.0f;
    for (int b = l; b < nb; b += 32)
        s += g_bsum[b*3 + j] * __expf(g_bmax[b*3 + j] - m);
    s = warpSum(s);
    if (l == 0) g_cls[j] = m + logf(s);
}

__global__ void k_final(float* __restrict__ out, int batch) {
    int i = blockIdx.x * blockDim.x + threadIdx.x;
    if (i >= batch * 3) return;
    out[i] -= g_cls[i % 3];
}

// ---------------- launch ------------------------------------------------------
extern "C" void kernel_launch(void* const* d_in, const int* in_sizes, int n_in,
                              void* d_out, int out_size) {
    const float* embed  = (const float*)d_in[0];
    const float* beta   = (const float*)d_in[1];
    const float* w0     = (const float*)d_in[2];
    const float* b0     = (const float*)d_in[3];
    const float* w1     = (const float*)d_in[4];
    const float* b1     = (const float*)d_in[5];
    const float* w2     = (const float*)d_in[6];
    const float* b2     = (const float*)d_in[7];
    const int*   eidx   = (const int*)d_in[8];
    const int*   home   = (const int*)d_in[9];
    const int*   away   = (const int*)d_in[10];
    float* out = (float*)d_out;

    const int n      = in_sizes[0] / D;          // 200000
    const int nedges = in_sizes[8] / 2;          // 3200000
    const int etot   = nedges + n;
    const int batch  = in_sizes[9];              // 500000

    const int* es = eidx;
    const int* ed = eidx + nedges;

    float* x1; cudaGetSymbolAddress((void**)&x1, g_x1);
    float* x2; cudaGetSymbolAddress((void**)&x2, g_x2);

    const int TB = 256;
    int gN   = (n + TB - 1) / TB;
    int gE   = (etot + TB - 1) / TB;
    int gB   = (batch + TB - 1) / TB;
    int gB3  = (batch * 3 + TB - 1) / TB;
    int gW   = (n * 32 + TB - 1) / TB;           // warp per dst
    int nsb  = (n + SCAN_BLK - 1) / SCAN_BLK;    // scan blocks (196)

    // ---- CSR build (shared by both layers) ----
    k_zero_deg<<<gN, TB>>>(n);
    k_count<<<gE, TB>>>(es, ed, nedges, etot);
    k_scan1<<<nsb, SCAN_BLK>>>(n);
    k_scan2<<<1, SCAN_BLK>>>(nsb);
    k_scan3<<<gN, TB>>>(n, etot);
    k_scatter<<<gE, TB>>>(es, ed, nedges, etot);

    // ---- layer 1 (input = embed) ----
    k_norm0<<<gN, TB>>>(embed, n);
    k_layer<1><<<gW, TB>>>(beta, 0, x1, n);      // writes leaky(x1), refreshes xn/norm

    // ---- layer 2 ----
    k_layer<0><<<gW, TB>>>(beta, 1, x2, n);      // writes leaky(x2)

    // ---- MLP + log_softmax(dim=0) ----
    k_mlp_stats<<<gB, TB>>>(x2, home, away, w0, b0, w1, b1, w2, b2, out, batch);
    k_colfix<<<1, 96>>>(gB);
    k_final<<<gB3, TB>>>(out, batch);
}